// round 1
// baseline (speedup 1.0000x reference)
#include <cuda_runtime.h>
#include <cstdint>
#include <cstddef>

#define BB 16
#define SS 4096
#define DD 256
#define CL 8
#define ROWS_PER_CTA (DD / CL)          // 32
#define TPR 16                          // threads per row
#define NTHREADS (ROWS_PER_CTA * TPR)   // 512
#define CPT (DD / TPR)                  // 16 cols per thread

// per-(b,t) scalar: eta * (1 - 1/n) * (1/n), n = max(||x_t||, 1e-6)
__device__ float g_coef[BB * SS];

// ---------------------------------------------------------------------------
// Kernel A: precompute per-step coefficients (norm-dependent scalars)
// ---------------------------------------------------------------------------
__global__ void coef_kernel(const float* __restrict__ x,
                            const float* __restrict__ eta_raw) {
    float eta = 0.2f / (1.0f + __expf(-eta_raw[0]));
    int warp  = (blockIdx.x * blockDim.x + threadIdx.x) >> 5;
    int lane  = threadIdx.x & 31;
    int nwarp = (gridDim.x * blockDim.x) >> 5;
    for (int row = warp; row < BB * SS; row += nwarp) {
        const float4* xr = reinterpret_cast<const float4*>(x + (size_t)row * DD);
        float4 a = xr[lane];
        float4 b = xr[lane + 32];
        float ss = a.x*a.x + a.y*a.y + a.z*a.z + a.w*a.w
                 + b.x*b.x + b.y*b.y + b.z*b.z + b.w*b.w;
        #pragma unroll
        for (int k = 16; k; k >>= 1) ss += __shfl_xor_sync(0xffffffffu, ss, k);
        if (lane == 0) {
            float n   = fmaxf(sqrtf(ss), 1e-6f);
            float inv = 1.0f / n;
            g_coef[row] = eta * (1.0f - inv) * inv;
        }
    }
}

// ---------------------------------------------------------------------------
// Kernel B: persistent scan. One 8-CTA cluster per batch, M in registers.
// ---------------------------------------------------------------------------
__global__ void __cluster_dims__(CL, 1, 1) __launch_bounds__(NTHREADS, 1)
scan_kernel(const float* __restrict__ x,
            const float* __restrict__ Minit,
            const float* __restrict__ alpha_raw,
            float* __restrict__ out) {
    __shared__ float warpfr[NTHREADS / 32];
    __shared__ float frbox[2][CL];

    unsigned rank;
    asm("mov.u32 %0, %%cluster_ctarank;" : "=r"(rank));
    int batch = blockIdx.x / CL;
    int tid   = threadIdx.x;
    int row_l = tid >> 4;         // 0..31
    int lir   = tid & 15;         // lane-in-row
    int row_g = (int)rank * ROWS_PER_CTA + row_l;
    int cs    = lir * CPT;

    float alpha = 0.5f + 0.5f / (1.0f + __expf(-alpha_raw[0]));

    // Load M_init fragment into registers
    float m[CPT];
    {
        const float4* mi = reinterpret_cast<const float4*>(Minit + (size_t)row_g * DD + cs);
        #pragma unroll
        for (int j = 0; j < CPT / 4; j++) {
            float4 v = mi[j];
            m[4*j+0] = v.x; m[4*j+1] = v.y; m[4*j+2] = v.z; m[4*j+3] = v.w;
        }
    }

    const float* xb    = x   + (size_t)batch * SS * DD;
    float*       outb  = out + (size_t)batch * SS * DD;
    float*       Mf    = out + (size_t)BB * SS * DD + (size_t)batch * DD * DD;
    const float* coefb = g_coef + batch * SS;

    // Preload x_0 and coef_0
    float xc[CPT];
    {
        const float4* xv = reinterpret_cast<const float4*>(xb + cs);
        #pragma unroll
        for (int j = 0; j < CPT / 4; j++) {
            float4 v = xv[j];
            xc[4*j+0] = v.x; xc[4*j+1] = v.y; xc[4*j+2] = v.z; xc[4*j+3] = v.w;
        }
    }
    float coef_c = coefb[0];

    float s = 1.0f;  // pending norm-clamp scale (M_t = s * N_stored)

    for (int t = 0; t < SS; t++) {
        // --- register double-buffer prefetch of x_{t+1}, coef_{t+1} ---
        float xn[CPT];
        float coef_n = 0.0f;
        #pragma unroll
        for (int j = 0; j < CPT; j++) xn[j] = 0.0f;
        if (t + 1 < SS) {
            const float4* xv = reinterpret_cast<const float4*>(xb + (size_t)(t + 1) * DD + cs);
            #pragma unroll
            for (int j = 0; j < CPT / 4; j++) {
                float4 v = xv[j];
                xn[4*j+0] = v.x; xn[4*j+1] = v.y; xn[4*j+2] = v.z; xn[4*j+3] = v.w;
            }
            coef_n = coefb[t + 1];
        }

        // --- pass 1: yraw = N @ x_t (row dot, reduce across 16 lanes) ---
        float y = 0.0f;
        #pragma unroll
        for (int j = 0; j < CPT; j++) y = fmaf(m[j], xc[j], y);
        #pragma unroll
        for (int k = 8; k; k >>= 1) y += __shfl_xor_sync(0xffffffffu, y, k);

        // --- receive s_{t-1}: cluster-barrier wait (overlapped with pass 1) ---
        if (t > 0) {
            asm volatile("barrier.cluster.wait.aligned;" ::: "memory");
            int par = (t - 1) & 1;
            float f = 0.0f;
            #pragma unroll
            for (int r = 0; r < CL; r++) f += frbox[par][r];
            float fro = sqrtf(f);
            s = fminf(15.0f / (fro + 1e-6f), 1.0f);
        }

        // --- output ---
        if (lir == 0) outb[(size_t)t * DD + row_g] = s * y;

        // --- pass 2: fused decay + rank-1 update + Frobenius accumulation ---
        float as = alpha * s;
        float g  = coef_c * s * y;
        float fr = 0.0f;
        #pragma unroll
        for (int j = 0; j < CPT; j++) {
            float nm = fmaf(g, xc[j], as * m[j]);
            m[j] = nm;
            fr = fmaf(nm, nm, fr);
        }

        // --- CTA-level Frobenius reduction ---
        #pragma unroll
        for (int k = 16; k; k >>= 1) fr += __shfl_xor_sync(0xffffffffu, fr, k);
        if ((tid & 31) == 0) warpfr[tid >> 5] = fr;
        __syncthreads();
        if (tid < 32) {
            float v = (tid < NTHREADS / 32) ? warpfr[tid] : 0.0f;
            #pragma unroll
            for (int k = 8; k; k >>= 1) v += __shfl_xor_sync(0xffffffffu, v, k);
            if (tid == 0) {
                int par = t & 1;
                uint32_t laddr = (uint32_t)__cvta_generic_to_shared(&frbox[par][rank]);
                #pragma unroll
                for (int r = 0; r < CL; r++) {
                    uint32_t raddr;
                    asm volatile("mapa.shared::cluster.u32 %0, %1, %2;"
                                 : "=r"(raddr) : "r"(laddr), "r"(r));
                    asm volatile("st.shared::cluster.f32 [%0], %1;"
                                 :: "r"(raddr), "f"(v) : "memory");
                }
            }
        }
        // release-arrive publishes thread 0's DSMEM stores to all peers
        asm volatile("barrier.cluster.arrive.aligned;" ::: "memory");

        // rotate double buffers
        #pragma unroll
        for (int j = 0; j < CPT; j++) xc[j] = xn[j];
        coef_c = coef_n;
    }

    // --- final pending scale, write M_final ---
    asm volatile("barrier.cluster.wait.aligned;" ::: "memory");
    {
        int par = (SS - 1) & 1;
        float f = 0.0f;
        #pragma unroll
        for (int r = 0; r < CL; r++) f += frbox[par][r];
        float fro = sqrtf(f);
        s = fminf(15.0f / (fro + 1e-6f), 1.0f);
    }
    float4* mo = reinterpret_cast<float4*>(Mf + (size_t)row_g * DD + cs);
    #pragma unroll
    for (int j = 0; j < CPT / 4; j++) {
        float4 v;
        v.x = s * m[4*j+0]; v.y = s * m[4*j+1];
        v.z = s * m[4*j+2]; v.w = s * m[4*j+3];
        mo[j] = v;
    }
}

// ---------------------------------------------------------------------------
// Launch: inputs per metadata order: x [B,S,D] f32, M_init [D,D] f32,
// eta_raw [1] f32, alpha_raw [1] f32. Output: outs [B,S,D] then M_final [B,D,D].
// ---------------------------------------------------------------------------
extern "C" void kernel_launch(void* const* d_in, const int* in_sizes, int n_in,
                              void* d_out, int out_size) {
    const float* x         = (const float*)d_in[0];
    const float* M_init    = (const float*)d_in[1];
    const float* eta_raw   = (const float*)d_in[2];
    const float* alpha_raw = (const float*)d_in[3];
    float*       out       = (float*)d_out;

    coef_kernel<<<256, 256>>>(x, eta_raw);
    scan_kernel<<<BB * CL, NTHREADS>>>(x, M_init, alpha_raw, out);
}